// round 8
// baseline (speedup 1.0000x reference)
#include <cuda_runtime.h>

#define V      10
#define L      45
#define NCOEF  14
#define RPB    64           // rows per block
#define TPB    256          // 4 threads per row
#define LSTR   49           // s_lam row stride (odd -> conflict-free)

// dynamic smem (bytes): pw 7920 | p 2520 | x 2816 | lam 12544 = 25800
#define SMEM_BYTES 25800

__device__ __forceinline__ float warp_sum(float v) {
#pragma unroll
    for (int o = 16; o > 0; o >>= 1) v += __shfl_down_sync(0xffffffffu, v, o);
    return v;
}

// M element value for runtime ij (arithmetic only, no tables)
__device__ __forceinline__ float mval(const float* __restrict__ lr, int ij) {
    int i = ij / 10;                 // const-divisor -> IMAD sequence
    int j = ij - i * 10;
    int m = (i * (i - 1)) / 2 + j;   // in [0,45] for all ij -> safe padded read
    float lv = lr[m];
    return (i == j) ? 1.0f : ((i > j) ? lv : 0.0f);
}

__global__ __launch_bounds__(TPB, 6)
void decor_kernel(const float* __restrict__ x,
                  const float* __restrict__ log_d,
                  const float* __restrict__ params,
                  float* __restrict__ out_all,
                  int n_rows)
{
    extern __shared__ unsigned char smem_raw[];
    float4* s_pw  = (float4*)smem_raw;             // [L][11] shifted windows
    float*  s_p   = (float*)(s_pw + L * 11);       // raw params [14][45]
    float*  s_x   = s_p + NCOEF * L;               // [RPB][11]
    float*  s_lam = s_x + RPB * 11;                // [RPB][LSTR]

    const int t = threadIdx.x;
    const int nblocks_main = (int)gridDim.x - 1;

    // ---------------- penalty block (last block) ----------------
    if ((int)blockIdx.x == nblocks_main) {
        float* sp  = s_p;
        float* red = s_x;
        for (int i = t; i < NCOEF * L; i += TPB) sp[i] = params[i];
        __syncthreads();
        float par = 0.f, fir = 0.f, sec = 0.f;
        for (int i = t; i < NCOEF * L; i += TPB) { float v = sp[i]; par += v * v; }
        for (int i = t; i < (NCOEF - 1) * L; i += TPB) { float d = sp[i + L] - sp[i]; fir += d * d; }
        for (int i = t; i < (NCOEF - 2) * L; i += TPB) {
            float d = sp[i + 2 * L] - 2.f * sp[i + L] + sp[i];
            sec += d * d;
        }
        par = warp_sum(par); fir = warp_sum(fir); sec = warp_sum(sec);
        int lane = t & 31, w = t >> 5;
        if (lane == 0) { red[0 * 8 + w] = sec; red[1 * 8 + w] = fir; red[2 * 8 + w] = par; }
        __syncthreads();
        if (w == 0) {
            float s = (lane < 8) ? red[0 * 8 + lane] : 0.f;
            float f = (lane < 8) ? red[1 * 8 + lane] : 0.f;
            float p = (lane < 8) ? red[2 * 8 + lane] : 0.f;
            s = warp_sum(s); f = warp_sum(f); p = warp_sum(p);
            if (lane == 0) {
                float* tail = out_all + (size_t)n_rows * (V + V * V + V);
                tail[0] = s; tail[1] = f; tail[2] = p;
            }
        }
        return;
    }

    // ---------------- main blocks ----------------
    const int base = (int)blockIdx.x * RPB;
    const int nr = min(RPB, n_rows - base);
    const int r = t & (RPB - 1);     // row within block
    const int q = t >> 6;            // quarter 0..3 (warp-uniform)

    // log_d passthrough (independent)
    {
        float* ldo = out_all + (size_t)n_rows * (V + V * V) + (size_t)base * V;
        const float* ldi = log_d + (size_t)base * V;
        int nfl = nr * V;
        if ((nfl & 3) == 0) {
            const float4* s4 = (const float4*)ldi;
            float4* d4 = (float4*)ldo;
            for (int g = t; g < nfl / 4; g += TPB) d4[g] = s4[g];
        } else {
            for (int g = t; g < nfl; g += TPB) ldo[g] = ldi[g];
        }
    }

    for (int i = t; i < NCOEF * L; i += TPB) s_p[i] = params[i];
    for (int i = t; i < nr * V; i += TPB) {
        int rr = i / V, c = i - rr * V;
        s_x[rr * 11 + c] = x[(size_t)base * V + i];
    }
    __syncthreads();

    // shifted windows: s_pw[l*11+jj] = params[jj..jj+3][l]
    for (int i = t; i < L * 11; i += TPB) {
        int l = i / 11, jj = i - l * 11;
        s_pw[i] = make_float4(s_p[jj * L + l], s_p[(jj + 1) * L + l],
                              s_p[(jj + 2) * L + l], s_p[(jj + 3) * L + l]);
    }
    __syncthreads();

    // -------- spline: 4 threads per row, j == q (mod 4) --------
    float xr[V];
    if (r < nr) {
#pragma unroll
        for (int c = 0; c < V; c++) xr[c] = s_x[r * 11 + c];

        const float INV_D = 11.0f / 10.0f;   // knot spacing d = 10/11
        const float k6 = 1.0f / 6.0f;
        float* lr = s_lam + r * LSTR;

#define SPLINE_J(jc)                                                          \
        do {                                                                  \
            float xc = fminf(fmaxf(xr[jc], -5.0f), 5.0f);                     \
            float tt = (xc + 5.0f) * INV_D;                                   \
            float fj = fminf(floorf(tt), 10.0f);                              \
            float u  = tt - fj;                                               \
            int   jj = (int)fj;                                               \
            float um = 1.0f - u;                                              \
            float u2 = u * u, u3 = u2 * u;                                    \
            float w0 = um * um * um * k6;                                     \
            float w1 = (3.0f * u3 - 6.0f * u2 + 4.0f) * k6;                   \
            float w2 = (-3.0f * u3 + 3.0f * u2 + 3.0f * u + 1.0f) * k6;       \
            float w3 = u3 * k6;                                               \
            _Pragma("unroll")                                                 \
            for (int i = jc + 1; i < V; i++) {                                \
                const int l = (i * (i - 1)) / 2 + jc;                         \
                float4 p = s_pw[l * 11 + jj];                                 \
                lr[l] = w0 * p.x + w1 * p.y + w2 * p.z + w3 * p.w;            \
            }                                                                 \
        } while (0)

        switch (q) {
            case 0: SPLINE_J(0); SPLINE_J(4); SPLINE_J(8); break;
            case 1: SPLINE_J(1); SPLINE_J(5); break;
            case 2: SPLINE_J(2); SPLINE_J(6); break;
            default: SPLINE_J(3); SPLINE_J(7); break;
        }
#undef SPLINE_J
    }
    __syncthreads();

    // -------- out: i == q (mod 4), xr reused from registers --------
    if (r < nr) {
        const float* lr = s_lam + r * LSTR;
        float* orow = out_all + (size_t)(base + r) * V;

#define OUT_I(ic)                                                             \
        do {                                                                  \
            float acc = xr[ic];                                               \
            _Pragma("unroll")                                                 \
            for (int j = 0; j < ic; j++)                                      \
                acc += lr[(ic * (ic - 1)) / 2 + j] * xr[j];                   \
            orow[ic] = acc;                                                   \
        } while (0)

        switch (q) {
            case 0: OUT_I(0); OUT_I(4); OUT_I(8); break;
            case 1: OUT_I(1); OUT_I(5); OUT_I(9); break;
            case 2: OUT_I(2); OUT_I(6); break;
            default: OUT_I(3); OUT_I(7); break;
        }
#undef OUT_I
    }

    // -------- M: fused coalesced writer straight from s_lam --------
    {
        float4* Mb4 = (float4*)(out_all + (size_t)n_rows * V) + (size_t)base * 25;
        const int nq = nr * 25;
        for (int g = t; g < nq; g += TPB) {
            int row = g / 25;
            int col = g - row * 25;
            const float* lr = s_lam + row * LSTR;
            int ij = col * 4;
            float4 v;
            v.x = mval(lr, ij + 0);
            v.y = mval(lr, ij + 1);
            v.z = mval(lr, ij + 2);
            v.w = mval(lr, ij + 3);
            Mb4[g] = v;              // contiguous across the block
        }
    }
}

extern "C" void kernel_launch(void* const* d_in, const int* in_sizes, int n_in,
                              void* d_out, int out_size)
{
    const float* x      = (const float*)d_in[0];
    const float* log_d  = (const float*)d_in[1];
    const float* params = (const float*)d_in[2];
    float* out_all = (float*)d_out;

    cudaFuncSetAttribute((const void*)decor_kernel,
                         cudaFuncAttributeMaxDynamicSharedMemorySize, SMEM_BYTES);

    int n_rows = in_sizes[0] / V;
    int main_blocks = (n_rows + RPB - 1) / RPB;
    decor_kernel<<<main_blocks + 1, TPB, SMEM_BYTES>>>(x, log_d, params, out_all, n_rows);
}

// round 9
// speedup vs baseline: 1.0849x; 1.0849x over previous
#include <cuda_runtime.h>

#define V      10
#define L      45
#define NCOEF  14
#define RPB    64           // rows per block
#define TPB    256          // 4 threads per row
#define LSTR   49           // s_lam row stride; slots 46/47 hold 1.0/0.0

// dynamic smem (bytes): pw 7920 | p 2520 | x 2816 | lam 12544 | map 100 = 25900
#define SMEM_BYTES 25904

__device__ __forceinline__ float warp_sum(float v) {
#pragma unroll
    for (int o = 16; o > 0; o >>= 1) v += __shfl_down_sync(0xffffffffu, v, o);
    return v;
}

__global__ __launch_bounds__(TPB, 6)
void decor_kernel(const float* __restrict__ x,
                  const float* __restrict__ log_d,
                  const float* __restrict__ params,
                  float* __restrict__ out_all,
                  int n_rows)
{
    extern __shared__ unsigned char smem_raw[];
    float4*   s_pw  = (float4*)smem_raw;             // [L][11] shifted windows
    float*    s_p   = (float*)(s_pw + L * 11);       // raw params [14][45]
    float*    s_x   = s_p + NCOEF * L;               // [RPB][11]
    float*    s_lam = s_x + RPB * 11;                // [RPB][LSTR], 46->1.0, 47->0.0
    unsigned* s_map = (unsigned*)(s_lam + RPB * LSTR); // [25] packed 4x lam-index

    const int t = threadIdx.x;
    const int nblocks_main = (int)gridDim.x - 1;

    // ---------------- penalty block (last block) ----------------
    if ((int)blockIdx.x == nblocks_main) {
        float* sp  = s_p;
        float* red = s_x;
        for (int i = t; i < NCOEF * L; i += TPB) sp[i] = params[i];
        __syncthreads();
        float par = 0.f, fir = 0.f, sec = 0.f;
        for (int i = t; i < NCOEF * L; i += TPB) { float v = sp[i]; par += v * v; }
        for (int i = t; i < (NCOEF - 1) * L; i += TPB) { float d = sp[i + L] - sp[i]; fir += d * d; }
        for (int i = t; i < (NCOEF - 2) * L; i += TPB) {
            float d = sp[i + 2 * L] - 2.f * sp[i + L] + sp[i];
            sec += d * d;
        }
        par = warp_sum(par); fir = warp_sum(fir); sec = warp_sum(sec);
        int lane = t & 31, w = t >> 5;
        if (lane == 0) { red[0 * 8 + w] = sec; red[1 * 8 + w] = fir; red[2 * 8 + w] = par; }
        __syncthreads();
        if (w == 0) {
            float s = (lane < 8) ? red[0 * 8 + lane] : 0.f;
            float f = (lane < 8) ? red[1 * 8 + lane] : 0.f;
            float p = (lane < 8) ? red[2 * 8 + lane] : 0.f;
            s = warp_sum(s); f = warp_sum(f); p = warp_sum(p);
            if (lane == 0) {
                float* tail = out_all + (size_t)n_rows * (V + V * V + V);
                tail[0] = s; tail[1] = f; tail[2] = p;
            }
        }
        return;
    }

    // ---------------- main blocks ----------------
    const int base = (int)blockIdx.x * RPB;
    const int nr = min(RPB, n_rows - base);
    const int r = t & (RPB - 1);     // row within block
    const int q = t >> 6;            // quarter 0..3 (warp-uniform)

    // log_d: load now, store at the very end (latency overlapped with body)
    const int nld4 = (nr * V) / 4;   // nr*10 divisible by 4 only if nr even; handle tail scalar
    float4 ld4 = make_float4(0.f, 0.f, 0.f, 0.f);
    if (t < nld4) ld4 = ((const float4*)(log_d + (size_t)base * V))[t];

    // build packed M map: col c -> 4 lam-slot indices (46=diag->1, 47=upper->0)
    if (t < 25) {
        unsigned mw = 0;
#pragma unroll
        for (int s = 0; s < 4; s++) {
            int ij = 4 * t + s;
            int i = ij / 10, j = ij - 10 * i;
            int m = (i == j) ? 46 : ((i > j) ? (i * (i - 1)) / 2 + j : 47);
            mw |= (unsigned)m << (8 * s);
        }
        s_map[t] = mw;
    }

    for (int i = t; i < NCOEF * L; i += TPB) s_p[i] = params[i];
    for (int i = t; i < nr * V; i += TPB) {
        int rr = i / V, c = i - rr * V;
        s_x[rr * 11 + c] = x[(size_t)base * V + i];
    }
    __syncthreads();

    // shifted windows: s_pw[l*11+jj] = params[jj..jj+3][l]
    for (int i = t; i < L * 11; i += TPB) {
        int l = i / 11, jj = i - l * 11;
        s_pw[i] = make_float4(s_p[jj * L + l], s_p[(jj + 1) * L + l],
                              s_p[(jj + 2) * L + l], s_p[(jj + 3) * L + l]);
    }
    __syncthreads();

    // -------- spline: 4 threads per row, j == q (mod 4) --------
    float xr[V];
    if (r < nr) {
#pragma unroll
        for (int c = 0; c < V; c++) xr[c] = s_x[r * 11 + c];

        const float INV_D = 11.0f / 10.0f;   // knot spacing d = 10/11
        const float k6 = 1.0f / 6.0f;
        float* lr = s_lam + r * LSTR;

        if (q == 3) { lr[46] = 1.0f; lr[47] = 0.0f; }   // constants for the M map

#define SPLINE_J(jc)                                                          \
        do {                                                                  \
            float xc = fminf(fmaxf(xr[jc], -5.0f), 5.0f);                     \
            float tt = (xc + 5.0f) * INV_D;                                   \
            float fj = fminf(floorf(tt), 10.0f);                              \
            float u  = tt - fj;                                               \
            int   jj = (int)fj;                                               \
            float um = 1.0f - u;                                              \
            float u2 = u * u, u3 = u2 * u;                                    \
            float w0 = um * um * um * k6;                                     \
            float w1 = (3.0f * u3 - 6.0f * u2 + 4.0f) * k6;                   \
            float w2 = (-3.0f * u3 + 3.0f * u2 + 3.0f * u + 1.0f) * k6;       \
            float w3 = u3 * k6;                                               \
            _Pragma("unroll")                                                 \
            for (int i = jc + 1; i < V; i++) {                                \
                const int l = (i * (i - 1)) / 2 + jc;                         \
                float4 p = s_pw[l * 11 + jj];                                 \
                lr[l] = w0 * p.x + w1 * p.y + w2 * p.z + w3 * p.w;            \
            }                                                                 \
        } while (0)

        switch (q) {
            case 0: SPLINE_J(0); SPLINE_J(4); SPLINE_J(8); break;
            case 1: SPLINE_J(1); SPLINE_J(5); break;
            case 2: SPLINE_J(2); SPLINE_J(6); break;
            default: SPLINE_J(3); SPLINE_J(7); break;
        }
#undef SPLINE_J
    }
    __syncthreads();

    // -------- out: i == q (mod 4), xr reused from registers --------
    if (r < nr) {
        const float* lr = s_lam + r * LSTR;
        float* orow = out_all + (size_t)(base + r) * V;

#define OUT_I(ic)                                                             \
        do {                                                                  \
            float acc = xr[ic];                                               \
            _Pragma("unroll")                                                 \
            for (int j = 0; j < ic; j++)                                      \
                acc += lr[(ic * (ic - 1)) / 2 + j] * xr[j];                   \
            orow[ic] = acc;                                                   \
        } while (0)

        switch (q) {
            case 0: OUT_I(0); OUT_I(4); OUT_I(8); break;
            case 1: OUT_I(1); OUT_I(5); OUT_I(9); break;
            case 2: OUT_I(2); OUT_I(6); break;
            default: OUT_I(3); OUT_I(7); break;
        }
#undef OUT_I
    }

    // -------- M: packed-map coalesced writer (no div/sel per element) --------
    {
        float4* Mb4 = (float4*)(out_all + (size_t)n_rows * V) + (size_t)base * 25;
        const int nq = nr * 25;
        int g = t;
        int row = t / 25;            // one-time divide
        int col = t - row * 25;
        while (g < nq) {
            const float* lr = s_lam + row * LSTR;
            unsigned mp = s_map[col];
            float4 v;
            v.x = lr[mp & 0xffu];
            v.y = lr[(mp >> 8) & 0xffu];
            v.z = lr[(mp >> 16) & 0xffu];
            v.w = lr[mp >> 24];
            Mb4[g] = v;
            g += TPB;                // 256 = 10*25 + 6
            row += 10;
            col += 6;
            if (col >= 25) { col -= 25; row += 1; }
        }
    }

    // -------- log_d store (loaded at kernel start) --------
    {
        float* ldo = out_all + (size_t)n_rows * (V + V * V) + (size_t)base * V;
        if (t < nld4) ((float4*)ldo)[t] = ld4;
        // scalar tail (nr*V not divisible by 4 only on ragged last block)
        for (int g2 = nld4 * 4 + t; g2 < nr * V; g2 += TPB)
            ldo[g2] = log_d[(size_t)base * V + g2];
    }
}

extern "C" void kernel_launch(void* const* d_in, const int* in_sizes, int n_in,
                              void* d_out, int out_size)
{
    const float* x      = (const float*)d_in[0];
    const float* log_d  = (const float*)d_in[1];
    const float* params = (const float*)d_in[2];
    float* out_all = (float*)d_out;

    cudaFuncSetAttribute((const void*)decor_kernel,
                         cudaFuncAttributeMaxDynamicSharedMemorySize, SMEM_BYTES);

    int n_rows = in_sizes[0] / V;
    int main_blocks = (n_rows + RPB - 1) / RPB;
    decor_kernel<<<main_blocks + 1, TPB, SMEM_BYTES>>>(x, log_d, params, out_all, n_rows);
}